// round 12
// baseline (speedup 1.0000x reference)
#include <cuda_runtime.h>
#include <cstdint>

// LinearKoopmanLayer: per-(b,f) complex rotation of channel pair (2f, 2f+1).
// x: (B=256, 2F=128, T=1024) fp32, out same shape.
//   a = amp[f]^dt[b];  c = a*cos(freq[f]*dt[b]);  s = a*sin(freq[f]*dt[b])
//   out[b,2f,t]   = c*x0 - s*x1
//   out[b,2f+1,t] = s*x0 + c*x1
//
// R12 experiment: native 256-bit global accesses (ld/st.global.v8.f32,
// sm_100+/PTX 8.8) on the proven R4 shape. Halves instruction count and
// L1tex wavefronts per byte; tests whether longer per-instruction bursts
// improve the DRAM read/write-turnaround ceiling (stuck at ~74% across all
// float4 variants). Same bytes/thread as R4: 2 x v8 per row, 2 rows.
// 64 threads per (b,f) pair, 4 pairs per 256-thread CTA, grid 4096.
// Default cache policy (any .cs qualifier measured as regression).

#define B_DIM 256
#define F_DIM 64
#define T_DIM 1024
#define BF_PER_BLOCK 4

struct f8 { float v[8]; };

__device__ __forceinline__ f8 ldg_v8(const float* p) {
    f8 r;
    asm volatile("ld.global.v8.f32 {%0,%1,%2,%3,%4,%5,%6,%7}, [%8];"
                 : "=f"(r.v[0]), "=f"(r.v[1]), "=f"(r.v[2]), "=f"(r.v[3]),
                   "=f"(r.v[4]), "=f"(r.v[5]), "=f"(r.v[6]), "=f"(r.v[7])
                 : "l"(p));
    return r;
}

__device__ __forceinline__ void stg_v8(float* p, const f8& r) {
    asm volatile("st.global.v8.f32 [%0], {%1,%2,%3,%4,%5,%6,%7,%8};"
                 :: "l"(p),
                    "f"(r.v[0]), "f"(r.v[1]), "f"(r.v[2]), "f"(r.v[3]),
                    "f"(r.v[4]), "f"(r.v[5]), "f"(r.v[6]), "f"(r.v[7])
                 : "memory");
}

__global__ __launch_bounds__(256, 8)
void koopman_kernel(const float* __restrict__ x,
                    const float* __restrict__ delta_t,
                    const float* __restrict__ amplitudes,
                    const float* __restrict__ frequencies,
                    float* __restrict__ out) {
    const int bf = blockIdx.x * BF_PER_BLOCK + (threadIdx.x >> 6);  // b*64+f
    const int t0 = threadIdx.x & 63;
    const int b  = bf >> 6;
    const int f  = bf & 63;

    // Scalar loads first: longest dep chain (LDG -> pow -> sincos).
    const float d   = __ldg(&delta_t[b]);
    const float amp = __ldg(&amplitudes[f]);
    const float frq = __ldg(&frequencies[f]);

    // rows 2f, 2f+1 of batch b -> global rows 2*bf, 2*bf+1 (contiguous 2 KB)
    const size_t base = (size_t)bf * (2 * T_DIM);
    const float* __restrict__ x0 = x + base;          // row 2f
    const float* __restrict__ x1 = x0 + T_DIM;        // row 2f+1
    float* __restrict__ o0 = out + base;
    float* __restrict__ o1 = o0 + T_DIM;

    // Front-batch 4 x 256-bit loads (same 256 B/thread as R4, fewer instrs).
    // Offsets (t0 + 64*i)*8 floats = 32B-aligned; lanes consecutive -> each
    // warp instruction covers a contiguous 1 KB (8 sectors).
    f8 a0[2], a1[2];
#pragma unroll
    for (int i = 0; i < 2; i++) a0[i] = ldg_v8(x0 + (t0 + 64 * i) * 8);
#pragma unroll
    for (int i = 0; i < 2; i++) a1[i] = ldg_v8(x1 + (t0 + 64 * i) * 8);

    // Coefficient: once per thread, fast intrinsics (err << 1e-3 budget).
    const float a = __powf(amp, d);         // amp in [0.7,1.3], d in [0.5,2]
    float s, c;
    __sincosf(frq * d, &s, &c);             // ang in [0, 4*pi]
    c *= a;
    s *= a;

#pragma unroll
    for (int i = 0; i < 2; i++) {
        f8 r0, r1;
#pragma unroll
        for (int j = 0; j < 8; j++) {
            r0.v[j] = c * a0[i].v[j] - s * a1[i].v[j];
            r1.v[j] = s * a0[i].v[j] + c * a1[i].v[j];
        }
        stg_v8(o0 + (t0 + 64 * i) * 8, r0);
        stg_v8(o1 + (t0 + 64 * i) * 8, r1);
    }
}

extern "C" void kernel_launch(void* const* d_in, const int* in_sizes, int n_in,
                              void* d_out, int out_size) {
    const float* x           = (const float*)d_in[0];
    const float* delta_t     = (const float*)d_in[1];
    const float* amplitudes  = (const float*)d_in[2];
    const float* frequencies = (const float*)d_in[3];
    float* out = (float*)d_out;

    dim3 grid((B_DIM * F_DIM) / BF_PER_BLOCK);   // 4096 blocks
    dim3 block(256);
    koopman_kernel<<<grid, block>>>(x, delta_t, amplitudes, frequencies, out);
}

// round 13
// speedup vs baseline: 1.0535x; 1.0535x over previous
#include <cuda_runtime.h>
#include <cstdint>

// LinearKoopmanLayer: per-(b,f) complex rotation of channel pair (2f, 2f+1).
// x: (B=256, 2F=128, T=1024) fp32, out same shape.
//   a = amp[f]^dt[b];  c = a*cos(freq[f]*dt[b]);  s = a*sin(freq[f]*dt[b])
//   out[b,2f,t]   = c*x0 - s*x1
//   out[b,2f+1,t] = s*x0 + c*x1
//
// FINAL — exhaustive sweep results (kernel us):
//   grid/block: 16384x256 MLP2 36.7 | 4096x256 MLP8 35.9* | 2048x512 36.7
//               | 2048x256 MLP16 36.7
//   cache:      default 35.9* | stcs 37.5 | ldcs+stcs 46.9
//   width:      LDG.128 35.9* | v8.f32 256-bit 43.6 (L1tex wavefront replays)
//   (* = this kernel, reproduced 3x at 35.9-36.5)
// Pinned at the path-independent memory ceiling: 268.4 MB / 35.9us =
// 7.48 TB/s apparent L2 throughput; DRAM 74-75% = read/write-turnaround
// ceiling for a 50/50 fp32 stream. Traffic irreducible (each byte touched
// once). Compute pipes <6%, issue ~10% — no kernel-side lever remains.
//
// Layout: 64 threads per (b,f) pair, each thread 4 float4 per row at
// t0+{0,64,128,192} (warp-coalesced 128B sectors), MLP_p1=8 front-batched
// loads; 4 pairs per 256-thread CTA, grid 4096. Coefficient (pow+sincos)
// once per thread via fast intrinsics, hidden under outstanding loads.
// rel_err 4.0e-7 << 1e-3 budget.

#define B_DIM 256
#define F_DIM 64
#define T_DIM 1024
#define T_VEC (T_DIM / 4)      // 256 float4 per row
#define BF_PER_BLOCK 4

__global__ __launch_bounds__(256, 8)
void koopman_kernel(const float* __restrict__ x,
                    const float* __restrict__ delta_t,
                    const float* __restrict__ amplitudes,
                    const float* __restrict__ frequencies,
                    float* __restrict__ out) {
    const int bf = blockIdx.x * BF_PER_BLOCK + (threadIdx.x >> 6);  // b*64+f
    const int t0 = threadIdx.x & 63;
    const int b  = bf >> 6;
    const int f  = bf & 63;

    // Scalar loads first: they head the longest dep chain (LDG -> pow -> sincos).
    const float d   = __ldg(&delta_t[b]);
    const float amp = __ldg(&amplitudes[f]);
    const float frq = __ldg(&frequencies[f]);

    // rows 2f, 2f+1 of batch b -> global rows 2*bf, 2*bf+1 (contiguous 2 KB)
    const size_t base = (size_t)bf * (2 * T_DIM);
    const float4* __restrict__ x0 = reinterpret_cast<const float4*>(x + base);
    const float4* __restrict__ x1 = x0 + T_VEC;
    float4* __restrict__ o0 = reinterpret_cast<float4*>(out + base);
    float4* __restrict__ o1 = o0 + T_VEC;

    // Front-batch all 8 vector loads (MLP=8), default cache policy.
    float4 v0[4], v1[4];
#pragma unroll
    for (int i = 0; i < 4; i++) v0[i] = x0[t0 + 64 * i];
#pragma unroll
    for (int i = 0; i < 4; i++) v1[i] = x1[t0 + 64 * i];

    // Coefficient: once per thread, fast intrinsics (err << 1e-3 budget).
    const float a = __powf(amp, d);         // amp in [0.7,1.3], d in [0.5,2]
    float s, c;
    __sincosf(frq * d, &s, &c);             // ang in [0, 4*pi]
    c *= a;
    s *= a;

#pragma unroll
    for (int i = 0; i < 4; i++) {
        float4 r0, r1;
        r0.x = c * v0[i].x - s * v1[i].x;  r1.x = s * v0[i].x + c * v1[i].x;
        r0.y = c * v0[i].y - s * v1[i].y;  r1.y = s * v0[i].y + c * v1[i].y;
        r0.z = c * v0[i].z - s * v1[i].z;  r1.z = s * v0[i].z + c * v1[i].z;
        r0.w = c * v0[i].w - s * v1[i].w;  r1.w = s * v0[i].w + c * v1[i].w;
        o0[t0 + 64 * i] = r0;
        o1[t0 + 64 * i] = r1;
    }
}

extern "C" void kernel_launch(void* const* d_in, const int* in_sizes, int n_in,
                              void* d_out, int out_size) {
    const float* x           = (const float*)d_in[0];
    const float* delta_t     = (const float*)d_in[1];
    const float* amplitudes  = (const float*)d_in[2];
    const float* frequencies = (const float*)d_in[3];
    float* out = (float*)d_out;

    dim3 grid((B_DIM * F_DIM) / BF_PER_BLOCK);   // 4096 blocks
    dim3 block(256);
    koopman_kernel<<<grid, block>>>(x, delta_t, amplitudes, frequencies, out);
}